// round 11
// baseline (speedup 1.0000x reference)
#include <cuda_runtime.h>
#include <cuda_bf16.h>
#include <cstdint>

// DifferentiableExtrusion: B=4, N=32 polygons, P=32 edges, V=96 grid.
// out[b,z,y,x] = (z < hv[b]) * max_{n valid} sigmoid(-100 * sdf_n(x,y))
//
// R10: parity-bitmap precompute.
//  * Crossing parity for point gx is XOR over edges of (px(gx) < ix_e) — a
//    prefix predicate in gx. Precompute per (row, polygon) a 96-bit bitmap
//    (3 u32 chunks) via exact thresholds t_e and __reduce_xor_sync.
//    Inner loop: distance only (7 math ops/point/edge), parity = 1 bit test.
//  * Thresholds computed with the SAME float compare the inner loop used ->
//    parity bit-identical to validated R8 kernel. Distance path unchanged.
//  * Block (32,8), grid (96,4), 3 points/thread, early-exit vote kept.

#define V 96
#define NPOLY 32
#define PEDGE 32
#define NEDGES (NPOLY * PEDGE)   // 1024
#define SHARPNESS 100.0f
#define EPS 1e-8f
#define FLT_BIG 3.402823466e38f
#define DEEP_IN2 0.01f           // (0.1)^2 : sigmoid(100*0.1) = 1 - 4.5e-5

__device__ __forceinline__ unsigned prefix_mask(int k) {
    // bits [0, k) set, clamped to 32
    if (k <= 0)  return 0u;
    if (k >= 32) return 0xffffffffu;
    return (1u << k) - 1u;
}

__global__ __launch_bounds__(256, 4)
void extrusion_kernel(const float* __restrict__ polygons,     // [B,N,P,2]
                      const float* __restrict__ attributes,   // [B,8]
                      const float* __restrict__ validity,     // [B,N]
                      float* __restrict__ out)                // [B,V,V,V]
{
    __shared__ float4 sEA[NEDGES];       // x0, ex, ey, c1
    __shared__ float2 sEB[NEDGES];       // c0, vy
    __shared__ int    sT[NEDGES];        // crossing threshold t_e (0 if none)
    __shared__ unsigned sPar[NPOLY][3];  // 96-bit inside-parity bitmap per poly
    __shared__ float2 sRed[8][3][32];    // (negmax, posmin)
    __shared__ int    sList[NPOLY];
    __shared__ int    sNv;

    const int b  = blockIdx.y;
    const int gy = blockIdx.x;           // this CTA's grid row
    const int tx = threadIdx.x;          // 32 lanes
    const int ty = threadIdx.y;          // 8 polygon groups (warp id)
    const int tid = tx + 32 * ty;

    const float inv_vm1 = 1.0f / (float)(V - 1);
    const float py = (float)gy * inv_vm1;

    // ---- pass 1: per-(row,edge) invariants + crossing thresholds ----
    const float* pb = polygons + (size_t)b * NEDGES * 2;
    #pragma unroll
    for (int e = tid; e < NEDGES; e += 256) {
        int n = e >> 5;
        int p = e & 31;
        int p1 = (p + 1) & 31;
        float x0 = pb[(n * PEDGE + p ) * 2 + 0];
        float y0 = pb[(n * PEDGE + p ) * 2 + 1];
        float x1 = pb[(n * PEDGE + p1) * 2 + 0];
        float y1 = pb[(n * PEDGE + p1) * 2 + 1];
        float ex = x1 - x0;
        float ey = y1 - y0;
        float inv_esq = 1.0f / (ex * ex + ey * ey + EPS);
        float inv_dy  = 1.0f / (ey + EPS);
        float vy = py - y0;
        float cc1 = ex * inv_esq;
        float cc0 = (vy * ey - x0 * ex) * inv_esq;
        bool  yc  = (y0 <= py) != (y1 <= py);
        int t_e = 0;
        if (yc) {
            float ix = x0 + ex * (vy * inv_dy);   // same expr as validated kernel
            // exact threshold: t_e = #{gx : (float)gx * inv_vm1 < ix}
            int c = (int)ceilf(ix * 95.0f);
            c = min(max(c, 0), V);
            #pragma unroll
            for (int k = 0; k < 3; ++k)
                if (c < V && (float)c * inv_vm1 < ix) c++;
            #pragma unroll
            for (int k = 0; k < 3; ++k)
                if (c > 0 && !((float)(c - 1) * inv_vm1 < ix)) c--;
            t_e = c;
        }
        sEA[e] = make_float4(x0, ex, ey, cc1);
        sEB[e] = make_float2(cc0, vy);
        sT[e]  = t_e;
    }
    if (tid < 32) {
        bool v = (validity[b * NPOLY + tid] >= 0.5f);
        unsigned m = __ballot_sync(0xffffffffu, v);
        if (v) sList[__popc(m & ((1u << tid) - 1u))] = tid;
        if (tid == 0) sNv = __popc(m);
    }
    __syncthreads();

    // ---- pass 2: parity bitmaps (warp ty handles polys ty*4 .. ty*4+3) ----
    #pragma unroll
    for (int q = 0; q < 4; ++q) {
        int poly = ty * 4 + q;
        int te = sT[(poly << 5) + tx];         // lane = edge index
        unsigned r0 = __reduce_xor_sync(0xffffffffu, prefix_mask(te));
        unsigned r1 = __reduce_xor_sync(0xffffffffu, prefix_mask(te - 32));
        unsigned r2 = __reduce_xor_sync(0xffffffffu, prefix_mask(te - 64));
        if (tx == 0) {
            sPar[poly][0] = r0;
            sPar[poly][1] = r1;
            sPar[poly][2] = r2;
        }
    }
    __syncthreads();
    const int nv = sNv;

    // ---- 3 points of this row per thread ----
    const float px0 = (float)(tx     ) * inv_vm1;
    const float px1 = (float)(tx + 32) * inv_vm1;
    const float px2 = (float)(tx + 64) * inv_vm1;

    float ng0 = -1.0f, ng1 = -1.0f, ng2 = -1.0f;       // max d^2 inside
    float ps0 = FLT_BIG, ps1 = FLT_BIG, ps2 = FLT_BIG; // min d^2 outside

    for (int i = ty; i < nv; i += 8) {
        const int pn   = sList[i];
        const int base = pn << 5;
        const bool in0 = (sPar[pn][0] >> tx) & 1u;
        const bool in1 = (sPar[pn][1] >> tx) & 1u;
        const bool in2 = (sPar[pn][2] >> tx) & 1u;

        float m0 = FLT_BIG, m1 = FLT_BIG, m2 = FLT_BIG;
        #pragma unroll 4
        for (int p = 0; p < PEDGE; ++p) {
            float4 a  = sEA[base + p];     // x0, ex, ey, c1
            float2 bb = sEB[base + p];     // c0, vy
            {   // point 0
                float vx = px0 - a.x;
                float t  = __saturatef(fmaf(px0, a.w, bb.x));
                float dx = fmaf(-t, a.y, vx);
                float dy = fmaf(-t, a.z, bb.y);
                m0 = fminf(m0, fmaf(dy, dy, dx * dx));
            }
            {   // point 1
                float vx = px1 - a.x;
                float t  = __saturatef(fmaf(px1, a.w, bb.x));
                float dx = fmaf(-t, a.y, vx);
                float dy = fmaf(-t, a.z, bb.y);
                m1 = fminf(m1, fmaf(dy, dy, dx * dx));
            }
            {   // point 2
                float vx = px2 - a.x;
                float t  = __saturatef(fmaf(px2, a.w, bb.x));
                float dx = fmaf(-t, a.y, vx);
                float dy = fmaf(-t, a.z, bb.y);
                m2 = fminf(m2, fmaf(dy, dy, dx * dx));
            }
        }
        ng0 = in0 ? fmaxf(ng0, m0) : ng0;   ps0 = in0 ? ps0 : fminf(ps0, m0);
        ng1 = in1 ? fmaxf(ng1, m1) : ng1;   ps1 = in1 ? ps1 : fminf(ps1, m1);
        ng2 = in2 ? fmaxf(ng2, m2) : ng2;   ps2 = in2 ? ps2 : fminf(ps2, m2);
        // warp-uniform early exit: all 96 row-points deep inside
        if (__all_sync(0xffffffffu,
                       (ng0 > DEEP_IN2) & (ng1 > DEEP_IN2) & (ng2 > DEEP_IN2)))
            break;
    }

    // ---- combine the 8 polygon groups ----
    sRed[ty][0][tx] = make_float2(ng0, ps0);
    sRed[ty][1][tx] = make_float2(ng1, ps1);
    sRed[ty][2][tx] = make_float2(ng2, ps2);
    __syncthreads();

    float mres[3];
    #pragma unroll
    for (int c = 0; c < 3; ++c) {
        float ng = -1.0f, ps = FLT_BIG;
        #pragma unroll
        for (int g = 0; g < 8; ++g) {
            float2 r = sRed[g][c][tx];
            ng = fmaxf(ng, r.x);
            ps = fminf(ps, r.y);
        }
        bool inside = (ng >= 0.0f);
        float d   = sqrtf(inside ? ng : ps);
        float sdf = inside ? -d : d;
        // nv==0: ps=FLT_BIG -> exp -> inf -> m = 0  (matches ref)
        mres[c] = 1.0f / (1.0f + __expf(SHARPNESS * sdf));
    }

    // ---- fused z-extrusion: 12 z-slices per group, full row, coalesced ----
    float hraw = __ldg(&attributes[b * 8]);
    float hv = fminf(fmaxf(rintf(__saturatef(hraw) * (float)V), 1.0f), (float)V);
    int hvi = (int)hv;

    float* ob = out + (size_t)b * V * V * V + (size_t)gy * V;
    const int z0 = ty * 12;
    #pragma unroll 4
    for (int z = z0; z < z0 + 12; ++z) {
        float* row = ob + (size_t)z * (V * V);
        bool on = (z < hvi);
        row[tx     ] = on ? mres[0] : 0.0f;
        row[tx + 32] = on ? mres[1] : 0.0f;
        row[tx + 64] = on ? mres[2] : 0.0f;
    }
}

extern "C" void kernel_launch(void* const* d_in, const int* in_sizes, int n_in,
                              void* d_out, int out_size)
{
    const float* polygons   = (const float*)d_in[0];  // [4,32,32,2]
    const float* attributes = (const float*)d_in[1];  // [4,8]
    const float* validity   = (const float*)d_in[2];  // [4,32]
    float* out = (float*)d_out;                       // [4,96,96,96]

    dim3 grid(V, 4);             // (96, 4) = 384 CTAs, one row each
    dim3 block(32, 8);           // 256 threads, 8 polygon groups
    extrusion_kernel<<<grid, block>>>(polygons, attributes, validity, out);
}

// round 13
// speedup vs baseline: 1.1285x; 1.1285x over previous
#include <cuda_runtime.h>
#include <cuda_bf16.h>
#include <cstdint>

// DifferentiableExtrusion: B=4, N=32 polygons, P=32 edges, V=96 grid.
// out[b,z,y,x] = (z < hv[b]) * max_{n valid} sigmoid(-100 * sdf_n(x,y))
//
// R11: occupancy + critical-path attack (parity bitmap reverted).
//  * block (32,8,2) = 512 threads, grid (144,4) = 576 CTAs of 64 points.
//    8 polygon groups -> ~2 polys per group critical path.
//    2 CTAs/SM x 16 warps = 32 resident warps (~50% occ), ~2 full waves.
//  * Inner loop: folded t = sat(fma(px,c1,c0)); per-row (c0,vy) + ix tables;
//    parity via validated ix>px sentinel compare.
//  * smem ~44KB static (under 48KB limit).

#define V 96
#define NPOLY 32
#define PEDGE 32
#define NEDGES (NPOLY * PEDGE)   // 1024
#define SHARPNESS 100.0f
#define EPS 1e-8f
#define FLT_BIG 3.402823466e38f
#define DEEP_IN2 0.01f           // (0.1)^2 : sigmoid(100*0.1) = 1 - 4.5e-5

__global__ __launch_bounds__(512, 2)
void extrusion_kernel(const float* __restrict__ polygons,     // [B,N,P,2]
                      const float* __restrict__ attributes,   // [B,8]
                      const float* __restrict__ validity,     // [B,N]
                      float* __restrict__ out)                // [B,V,V,V]
{
    __shared__ float4 sEA[NEDGES];        // x0, ex, ey, c1          (16KB)
    __shared__ float2 sCV[2][NEDGES];     // per row: c0, vy         (16KB)
    __shared__ float  sIX[2][NEDGES];     // per row: ix sentinel    ( 8KB)
    __shared__ float2 sRed[2][8][32];     // (negmax, posmin)        ( 4KB)
    __shared__ int    sList[NPOLY];
    __shared__ int    sNv;

    const int b  = blockIdx.y;
    const int tx = threadIdx.x;           // 32 lanes
    const int ty = threadIdx.y;           // 8 polygon groups
    const int tz = threadIdx.z;           // 2 point chunks (rows)
    const int tid = tx + 32 * (ty + 8 * tz);

    const float inv_vm1 = 1.0f / (float)(V - 1);
    // 32-aligned chunks never straddle rows (96 = 3*32)
    const int gy0 = (blockIdx.x * 64     ) / V;
    const int gy1 = (blockIdx.x * 64 + 32) / V;

    // ---- per-(row,edge) precompute ----
    const float* pb = polygons + (size_t)b * NEDGES * 2;
    #pragma unroll
    for (int e = tid; e < 2 * NEDGES; e += 512) {
        int r   = e >> 10;                // row 0/1
        int idx = e & (NEDGES - 1);
        int n = idx >> 5;
        int p = idx & 31;
        int p1 = (p + 1) & 31;
        float x0 = pb[(n * PEDGE + p ) * 2 + 0];
        float y0 = pb[(n * PEDGE + p ) * 2 + 1];
        float x1 = pb[(n * PEDGE + p1) * 2 + 0];
        float y1 = pb[(n * PEDGE + p1) * 2 + 1];
        float ex = x1 - x0;
        float ey = y1 - y0;
        float inv_esq = 1.0f / (ex * ex + ey * ey + EPS);
        float inv_dy  = 1.0f / (ey + EPS);
        float py = (float)(r ? gy1 : gy0) * inv_vm1;
        float vy = py - y0;
        float c1 = ex * inv_esq;
        float c0 = (vy * ey - x0 * ex) * inv_esq;
        bool  yc = (y0 <= py) != (y1 <= py);
        float ix = yc ? (x0 + ex * (vy * inv_dy)) : -1.0f;   // never > px in [0,1]
        if (r == 0) sEA[idx] = make_float4(x0, ex, ey, c1);
        sCV[r][idx] = make_float2(c0, vy);
        sIX[r][idx] = ix;
    }
    if (tid < 32) {
        bool v = (validity[b * NPOLY + tid] >= 0.5f);
        unsigned m = __ballot_sync(0xffffffffu, v);
        if (v) sList[__popc(m & ((1u << tid) - 1u))] = tid;
        if (tid == 0) sNv = __popc(m);
    }
    __syncthreads();
    const int nv = sNv;

    // ---- this thread's grid point ----
    const int pidx = blockIdx.x * 64 + tz * 32 + tx;
    const int gy = tz ? gy1 : gy0;
    const int gx = pidx - gy * V;
    const float px = (float)gx * inv_vm1;

    const float2* __restrict__ cv  = sCV[tz];
    const float*  __restrict__ ixs = sIX[tz];

    float negmax = -1.0f;        // max d^2 among INSIDE polygons
    float posmin = FLT_BIG;      // min d^2 among OUTSIDE polygons

    for (int i = ty; i < nv; i += 8) {
        const int base = sList[i] << 5;
        float mda = FLT_BIG, mdb = FLT_BIG;
        int cnt = 0;
        #pragma unroll
        for (int p = 0; p < PEDGE; p += 2) {
            {   // edge p
                float4 a  = sEA[base + p];
                float2 f2 = cv[base + p];
                float ix  = ixs[base + p];
                float vx = px - a.x;
                float t  = __saturatef(fmaf(px, a.w, f2.x));
                float dx = fmaf(-t, a.y, vx);
                float dy = fmaf(-t, a.z, f2.y);
                mda = fminf(mda, fmaf(dy, dy, dx * dx));
                cnt += (ix > px);
            }
            {   // edge p+1
                float4 a  = sEA[base + p + 1];
                float2 f2 = cv[base + p + 1];
                float ix  = ixs[base + p + 1];
                float vx = px - a.x;
                float t  = __saturatef(fmaf(px, a.w, f2.x));
                float dx = fmaf(-t, a.y, vx);
                float dy = fmaf(-t, a.z, f2.y);
                mdb = fminf(mdb, fmaf(dy, dy, dx * dx));
                cnt += (ix > px);
            }
        }
        float min_d2 = fminf(mda, mdb);
        if (cnt & 1) negmax = fmaxf(negmax, min_d2);
        else         posmin = fminf(posmin, min_d2);
        // warp-uniform early exit: all lanes deep inside -> m within 1e-4 of 1
        if (__all_sync(0xffffffffu, negmax > DEEP_IN2)) break;
    }

    // ---- combine the 8 polygon groups ----
    sRed[tz][ty][tx] = make_float2(negmax, posmin);
    __syncthreads();

    float ng = -1.0f, ps = FLT_BIG;
    #pragma unroll
    for (int g = 0; g < 8; ++g) {
        float2 r = sRed[tz][g][tx];
        ng = fmaxf(ng, r.x);
        ps = fminf(ps, r.y);
    }

    bool inside = (ng >= 0.0f);
    float d   = sqrtf(inside ? ng : ps);
    float sdf = inside ? -d : d;
    // nv==0: ps=FLT_BIG -> exp -> inf -> m = 0  (matches ref)
    float m = 1.0f / (1.0f + __expf(SHARPNESS * sdf));

    // ---- fused z-extrusion: 12 z-slices per group-thread, coalesced ----
    float hraw = __ldg(&attributes[b * 8]);
    float hv = fminf(fmaxf(rintf(__saturatef(hraw) * (float)V), 1.0f), (float)V);
    int hvi = (int)hv;

    float* col = out + (size_t)b * V * V * V + (size_t)gy * V + gx;
    const int z0 = ty * 12;
    #pragma unroll 4
    for (int z = z0; z < z0 + 12; ++z) {
        col[(size_t)z * (V * V)] = (z < hvi) ? m : 0.0f;
    }
}

extern "C" void kernel_launch(void* const* d_in, const int* in_sizes, int n_in,
                              void* d_out, int out_size)
{
    const float* polygons   = (const float*)d_in[0];  // [4,32,32,2]
    const float* attributes = (const float*)d_in[1];  // [4,8]
    const float* validity   = (const float*)d_in[2];  // [4,32]
    float* out = (float*)d_out;                       // [4,96,96,96]

    dim3 grid(V * V / 64, 4);    // (144, 4) = 576 CTAs, 64 points each
    dim3 block(32, 8, 2);        // 512 threads, 8 polygon groups
    extrusion_kernel<<<grid, block>>>(polygons, attributes, validity, out);
}

// round 15
// speedup vs baseline: 1.1591x; 1.0271x over previous
#include <cuda_runtime.h>
#include <cuda_bf16.h>
#include <cstdint>

// DifferentiableExtrusion: B=4, N=32 polygons, P=32 edges, V=96 grid.
// out[b,z,y,x] = (z < hv[b]) * max_{n valid} sigmoid(-100 * sdf_n(x,y))
//
// R13: R8 inner loop (best smem-crossbar economy: 2xLDS.128 per edge serving
// 3 points) + 512-thread CTAs to fix occupancy without touching the grid.
//  * 1 CTA = 1 row (96 points), block (32,16): 16 polygon groups,
//    3 points per thread (x = tx, tx+32, tx+64).
//  * ceil(nv/16) = 1-2 polygons per group -> short, balanced critical path.
//  * ~2 CTAs/SM x 16 warps -> ~32-48 resident warps/SM.
//  * Distance + parity arithmetic bit-identical to validated R8 kernel.

#define V 96
#define NPOLY 32
#define PEDGE 32
#define NEDGES (NPOLY * PEDGE)   // 1024
#define SHARPNESS 100.0f
#define EPS 1e-8f
#define FLT_BIG 3.402823466e38f
#define DEEP_IN2 0.01f           // (0.1)^2 : sigmoid(100*0.1) = 1 - 4.5e-5

__global__ __launch_bounds__(512, 2)
void extrusion_kernel(const float* __restrict__ polygons,     // [B,N,P,2]
                      const float* __restrict__ attributes,   // [B,8]
                      const float* __restrict__ validity,     // [B,N]
                      float* __restrict__ out)                // [B,V,V,V]
{
    __shared__ float4 sEA[NEDGES];       // x0, ex, ey, c1          (16KB)
    __shared__ float4 sEB[NEDGES];       // c0, vy, ix, --          (16KB)
    __shared__ float2 sRed[16][3][32];   // (negmax, posmin)        (12KB)
    __shared__ int    sList[NPOLY];
    __shared__ int    sNv;

    const int b  = blockIdx.y;
    const int gy = blockIdx.x;           // this CTA's grid row
    const int tx = threadIdx.x;          // 32 lanes
    const int ty = threadIdx.y;          // 16 polygon groups (warp id)
    const int tid = tx + 32 * ty;

    const float inv_vm1 = 1.0f / (float)(V - 1);
    const float py = (float)gy * inv_vm1;

    // ---- per-(row,edge) precompute into shared ----
    const float* pb = polygons + (size_t)b * NEDGES * 2;
    #pragma unroll
    for (int e = tid; e < NEDGES; e += 512) {
        int n = e >> 5;
        int p = e & 31;
        int p1 = (p + 1) & 31;
        float x0 = pb[(n * PEDGE + p ) * 2 + 0];
        float y0 = pb[(n * PEDGE + p ) * 2 + 1];
        float x1 = pb[(n * PEDGE + p1) * 2 + 0];
        float y1 = pb[(n * PEDGE + p1) * 2 + 1];
        float ex = x1 - x0;
        float ey = y1 - y0;
        float inv_esq = 1.0f / (ex * ex + ey * ey + EPS);
        float inv_dy  = 1.0f / (ey + EPS);
        float vy = py - y0;
        float cc1 = ex * inv_esq;
        float cc0 = (vy * ey - x0 * ex) * inv_esq;
        bool  yc = (y0 <= py) != (y1 <= py);
        float ix = yc ? (x0 + ex * (vy * inv_dy)) : -1.0f;   // sentinel: never > px
        sEA[e] = make_float4(x0, ex, ey, cc1);
        sEB[e] = make_float4(cc0, vy, ix, 0.0f);
    }
    if (tid < 32) {
        bool v = (validity[b * NPOLY + tid] >= 0.5f);
        unsigned m = __ballot_sync(0xffffffffu, v);
        if (v) sList[__popc(m & ((1u << tid) - 1u))] = tid;
        if (tid == 0) sNv = __popc(m);
    }
    __syncthreads();
    const int nv = sNv;

    // ---- 3 points of this row per thread ----
    const float px0 = (float)(tx     ) * inv_vm1;
    const float px1 = (float)(tx + 32) * inv_vm1;
    const float px2 = (float)(tx + 64) * inv_vm1;

    float ng0 = -1.0f, ng1 = -1.0f, ng2 = -1.0f;       // max d^2 inside
    float ps0 = FLT_BIG, ps1 = FLT_BIG, ps2 = FLT_BIG; // min d^2 outside

    for (int i = ty; i < nv; i += 16) {
        const int base = sList[i] << 5;
        float m0 = FLT_BIG, m1 = FLT_BIG, m2 = FLT_BIG;
        int   k0 = 0, k1 = 0, k2 = 0;
        #pragma unroll 4
        for (int p = 0; p < PEDGE; ++p) {
            float4 a  = sEA[base + p];     // x0, ex, ey, c1
            float4 bb = sEB[base + p];     // c0, vy, ix
            {   // point 0
                float vx = px0 - a.x;
                float t  = __saturatef(fmaf(px0, a.w, bb.x));
                float dx = fmaf(-t, a.y, vx);
                float dy = fmaf(-t, a.z, bb.y);
                m0 = fminf(m0, fmaf(dy, dy, dx * dx));
                k0 += (bb.z > px0);
            }
            {   // point 1
                float vx = px1 - a.x;
                float t  = __saturatef(fmaf(px1, a.w, bb.x));
                float dx = fmaf(-t, a.y, vx);
                float dy = fmaf(-t, a.z, bb.y);
                m1 = fminf(m1, fmaf(dy, dy, dx * dx));
                k1 += (bb.z > px1);
            }
            {   // point 2
                float vx = px2 - a.x;
                float t  = __saturatef(fmaf(px2, a.w, bb.x));
                float dx = fmaf(-t, a.y, vx);
                float dy = fmaf(-t, a.z, bb.y);
                m2 = fminf(m2, fmaf(dy, dy, dx * dx));
                k2 += (bb.z > px2);
            }
        }
        if (k0 & 1) ng0 = fmaxf(ng0, m0); else ps0 = fminf(ps0, m0);
        if (k1 & 1) ng1 = fmaxf(ng1, m1); else ps1 = fminf(ps1, m1);
        if (k2 & 1) ng2 = fmaxf(ng2, m2); else ps2 = fminf(ps2, m2);
        // warp-uniform early exit: all 96 row-points deep inside
        if (__all_sync(0xffffffffu,
                       (ng0 > DEEP_IN2) & (ng1 > DEEP_IN2) & (ng2 > DEEP_IN2)))
            break;
    }

    // ---- combine the 16 polygon groups ----
    sRed[ty][0][tx] = make_float2(ng0, ps0);
    sRed[ty][1][tx] = make_float2(ng1, ps1);
    sRed[ty][2][tx] = make_float2(ng2, ps2);
    __syncthreads();

    float mres[3];
    #pragma unroll
    for (int c = 0; c < 3; ++c) {
        float ng = -1.0f, ps = FLT_BIG;
        #pragma unroll
        for (int g = 0; g < 16; ++g) {
            float2 r = sRed[g][c][tx];
            ng = fmaxf(ng, r.x);
            ps = fminf(ps, r.y);
        }
        bool inside = (ng >= 0.0f);
        float d   = sqrtf(inside ? ng : ps);
        float sdf = inside ? -d : d;
        // nv==0: ps=FLT_BIG -> exp -> inf -> m = 0  (matches ref)
        mres[c] = 1.0f / (1.0f + __expf(SHARPNESS * sdf));
    }

    // ---- fused z-extrusion: 6 z-slices per group, full row, coalesced ----
    float hraw = __ldg(&attributes[b * 8]);
    float hv = fminf(fmaxf(rintf(__saturatef(hraw) * (float)V), 1.0f), (float)V);
    int hvi = (int)hv;

    float* ob = out + (size_t)b * V * V * V + (size_t)gy * V;
    const int z0 = ty * 6;
    #pragma unroll
    for (int z = z0; z < z0 + 6; ++z) {
        float* row = ob + (size_t)z * (V * V);
        bool on = (z < hvi);
        row[tx     ] = on ? mres[0] : 0.0f;
        row[tx + 32] = on ? mres[1] : 0.0f;
        row[tx + 64] = on ? mres[2] : 0.0f;
    }
}

extern "C" void kernel_launch(void* const* d_in, const int* in_sizes, int n_in,
                              void* d_out, int out_size)
{
    const float* polygons   = (const float*)d_in[0];  // [4,32,32,2]
    const float* attributes = (const float*)d_in[1];  // [4,8]
    const float* validity   = (const float*)d_in[2];  // [4,32]
    float* out = (float*)d_out;                       // [4,96,96,96]

    dim3 grid(V, 4);             // (96, 4) = 384 CTAs, one row each
    dim3 block(32, 16);          // 512 threads, 16 polygon groups
    extrusion_kernel<<<grid, block>>>(polygons, attributes, validity, out);
}

// round 16
// speedup vs baseline: 1.2102x; 1.0442x over previous
#include <cuda_runtime.h>
#include <cuda_bf16.h>
#include <cstdint>

// DifferentiableExtrusion: B=4, N=32 polygons, P=32 edges, V=96 grid.
// out[b,z,y,x] = (z < hv[b]) * max_{n valid} sigmoid(-100 * sdf_n(x,y))
//
// R15: single-wave residency + parity bitmap + 3-point amortized inner loop.
//  * block (32,12) = 384 thr, 1 CTA = 1 row, grid 384, launch_bounds(384,3)
//    -> 3 CTAs/SM resident = 444 >= 384: ONE wave, no 2x CTA tail.
//  * inner loop: distance only (LDS.128 + LDS.64 per edge, 3 points/thread);
//    crossing parity precomputed per (row, polygon) as 96-bit bitmap
//    (exact thresholds, bit-identical to validated R10 kernel).
//  * 12 polygon groups -> ceil(nv/12) ~ 2 polys/group critical path.

#define V 96
#define NPOLY 32
#define PEDGE 32
#define NEDGES (NPOLY * PEDGE)   // 1024
#define SHARPNESS 100.0f
#define EPS 1e-8f
#define FLT_BIG 3.402823466e38f
#define DEEP_IN2 0.01f           // (0.1)^2 : sigmoid(100*0.1) = 1 - 4.5e-5
#define NGRP 12

__device__ __forceinline__ unsigned prefix_mask(int k) {
    if (k <= 0)  return 0u;
    if (k >= 32) return 0xffffffffu;
    return (1u << k) - 1u;
}

__global__ __launch_bounds__(384, 3)
void extrusion_kernel(const float* __restrict__ polygons,     // [B,N,P,2]
                      const float* __restrict__ attributes,   // [B,8]
                      const float* __restrict__ validity,     // [B,N]
                      float* __restrict__ out)                // [B,V,V,V]
{
    __shared__ float4 sEA[NEDGES];        // x0, ex, ey, c1          (16KB)
    __shared__ float2 sEB[NEDGES];        // c0, vy                  ( 8KB)
    __shared__ int    sT[NEDGES];         // crossing threshold      ( 4KB)
    __shared__ unsigned sPar[NPOLY][3];   // 96-bit parity bitmaps
    __shared__ float2 sRed[NGRP][3][32];  // (negmax, posmin)        ( 9KB)
    __shared__ int    sList[NPOLY];
    __shared__ int    sNv;

    const int b  = blockIdx.y;
    const int gy = blockIdx.x;            // this CTA's grid row
    const int tx = threadIdx.x;           // 32 lanes
    const int ty = threadIdx.y;           // 12 polygon groups (warp id)
    const int tid = tx + 32 * ty;

    const float inv_vm1 = 1.0f / (float)(V - 1);
    const float py = (float)gy * inv_vm1;

    // ---- pass 1: per-(row,edge) invariants + crossing thresholds ----
    const float* pb = polygons + (size_t)b * NEDGES * 2;
    for (int e = tid; e < NEDGES; e += 384) {
        int n = e >> 5;
        int p = e & 31;
        int p1 = (p + 1) & 31;
        float x0 = pb[(n * PEDGE + p ) * 2 + 0];
        float y0 = pb[(n * PEDGE + p ) * 2 + 1];
        float x1 = pb[(n * PEDGE + p1) * 2 + 0];
        float y1 = pb[(n * PEDGE + p1) * 2 + 1];
        float ex = x1 - x0;
        float ey = y1 - y0;
        float inv_esq = 1.0f / (ex * ex + ey * ey + EPS);
        float inv_dy  = 1.0f / (ey + EPS);
        float vy = py - y0;
        float cc1 = ex * inv_esq;
        float cc0 = (vy * ey - x0 * ex) * inv_esq;
        bool  yc  = (y0 <= py) != (y1 <= py);
        int t_e = 0;
        if (yc) {
            float ix = x0 + ex * (vy * inv_dy);   // same expr as validated kernels
            // exact threshold: t_e = #{gx : (float)gx * inv_vm1 < ix}
            int c = (int)ceilf(ix * 95.0f);
            c = min(max(c, 0), V);
            #pragma unroll
            for (int k = 0; k < 3; ++k)
                if (c < V && (float)c * inv_vm1 < ix) c++;
            #pragma unroll
            for (int k = 0; k < 3; ++k)
                if (c > 0 && !((float)(c - 1) * inv_vm1 < ix)) c--;
            t_e = c;
        }
        sEA[e] = make_float4(x0, ex, ey, cc1);
        sEB[e] = make_float2(cc0, vy);
        sT[e]  = t_e;
    }
    if (tid < 32) {
        bool v = (validity[b * NPOLY + tid] >= 0.5f);
        unsigned m = __ballot_sync(0xffffffffu, v);
        if (v) sList[__popc(m & ((1u << tid) - 1u))] = tid;
        if (tid == 0) sNv = __popc(m);
    }
    __syncthreads();

    // ---- pass 2: parity bitmaps (warps round-robin over polygons) ----
    for (int poly = ty; poly < NPOLY; poly += NGRP) {
        int te = sT[(poly << 5) + tx];        // lane = edge index
        unsigned r0 = __reduce_xor_sync(0xffffffffu, prefix_mask(te));
        unsigned r1 = __reduce_xor_sync(0xffffffffu, prefix_mask(te - 32));
        unsigned r2 = __reduce_xor_sync(0xffffffffu, prefix_mask(te - 64));
        if (tx == 0) {
            sPar[poly][0] = r0;
            sPar[poly][1] = r1;
            sPar[poly][2] = r2;
        }
    }
    __syncthreads();
    const int nv = sNv;

    // ---- 3 points of this row per thread ----
    const float px0 = (float)(tx     ) * inv_vm1;
    const float px1 = (float)(tx + 32) * inv_vm1;
    const float px2 = (float)(tx + 64) * inv_vm1;

    float ng0 = -1.0f, ng1 = -1.0f, ng2 = -1.0f;       // max d^2 inside
    float ps0 = FLT_BIG, ps1 = FLT_BIG, ps2 = FLT_BIG; // min d^2 outside

    for (int i = ty; i < nv; i += NGRP) {
        const int pn   = sList[i];
        const int base = pn << 5;
        const bool in0 = (sPar[pn][0] >> tx) & 1u;
        const bool in1 = (sPar[pn][1] >> tx) & 1u;
        const bool in2 = (sPar[pn][2] >> tx) & 1u;

        float m0 = FLT_BIG, m1 = FLT_BIG, m2 = FLT_BIG;
        #pragma unroll 4
        for (int p = 0; p < PEDGE; ++p) {
            float4 a  = sEA[base + p];     // x0, ex, ey, c1
            float2 bb = sEB[base + p];     // c0, vy
            {   // point 0
                float vx = px0 - a.x;
                float t  = __saturatef(fmaf(px0, a.w, bb.x));
                float dx = fmaf(-t, a.y, vx);
                float dy = fmaf(-t, a.z, bb.y);
                m0 = fminf(m0, fmaf(dy, dy, dx * dx));
            }
            {   // point 1
                float vx = px1 - a.x;
                float t  = __saturatef(fmaf(px1, a.w, bb.x));
                float dx = fmaf(-t, a.y, vx);
                float dy = fmaf(-t, a.z, bb.y);
                m1 = fminf(m1, fmaf(dy, dy, dx * dx));
            }
            {   // point 2
                float vx = px2 - a.x;
                float t  = __saturatef(fmaf(px2, a.w, bb.x));
                float dx = fmaf(-t, a.y, vx);
                float dy = fmaf(-t, a.z, bb.y);
                m2 = fminf(m2, fmaf(dy, dy, dx * dx));
            }
        }
        ng0 = in0 ? fmaxf(ng0, m0) : ng0;   ps0 = in0 ? ps0 : fminf(ps0, m0);
        ng1 = in1 ? fmaxf(ng1, m1) : ng1;   ps1 = in1 ? ps1 : fminf(ps1, m1);
        ng2 = in2 ? fmaxf(ng2, m2) : ng2;   ps2 = in2 ? ps2 : fminf(ps2, m2);
        // warp-uniform early exit: all 96 row-points deep inside
        if (__all_sync(0xffffffffu,
                       (ng0 > DEEP_IN2) & (ng1 > DEEP_IN2) & (ng2 > DEEP_IN2)))
            break;
    }

    // ---- combine the 12 polygon groups ----
    sRed[ty][0][tx] = make_float2(ng0, ps0);
    sRed[ty][1][tx] = make_float2(ng1, ps1);
    sRed[ty][2][tx] = make_float2(ng2, ps2);
    __syncthreads();

    float mres[3];
    #pragma unroll
    for (int c = 0; c < 3; ++c) {
        float ng = -1.0f, ps = FLT_BIG;
        #pragma unroll
        for (int g = 0; g < NGRP; ++g) {
            float2 r = sRed[g][c][tx];
            ng = fmaxf(ng, r.x);
            ps = fminf(ps, r.y);
        }
        bool inside = (ng >= 0.0f);
        float d   = sqrtf(inside ? ng : ps);
        float sdf = inside ? -d : d;
        // nv==0: ps=FLT_BIG -> exp -> inf -> m = 0  (matches ref)
        mres[c] = 1.0f / (1.0f + __expf(SHARPNESS * sdf));
    }

    // ---- fused z-extrusion: 8 z-slices per group, full row, coalesced ----
    float hraw = __ldg(&attributes[b * 8]);
    float hv = fminf(fmaxf(rintf(__saturatef(hraw) * (float)V), 1.0f), (float)V);
    int hvi = (int)hv;

    float* ob = out + (size_t)b * V * V * V + (size_t)gy * V;
    const int z0 = ty * 8;
    #pragma unroll
    for (int z = z0; z < z0 + 8; ++z) {
        float* row = ob + (size_t)z * (V * V);
        bool on = (z < hvi);
        row[tx     ] = on ? mres[0] : 0.0f;
        row[tx + 32] = on ? mres[1] : 0.0f;
        row[tx + 64] = on ? mres[2] : 0.0f;
    }
}

extern "C" void kernel_launch(void* const* d_in, const int* in_sizes, int n_in,
                              void* d_out, int out_size)
{
    const float* polygons   = (const float*)d_in[0];  // [4,32,32,2]
    const float* attributes = (const float*)d_in[1];  // [4,8]
    const float* validity   = (const float*)d_in[2];  // [4,32]
    float* out = (float*)d_out;                       // [4,96,96,96]

    dim3 grid(V, 4);             // (96, 4) = 384 CTAs, one row each
    dim3 block(32, NGRP);        // 384 threads, 12 polygon groups
    extrusion_kernel<<<grid, block>>>(polygons, attributes, validity, out);
}